// round 4
// baseline (speedup 1.0000x reference)
#include <cuda_runtime.h>
#include <math.h>

// SenseEmbedding:
//  x:   [16384, 12] int32   -- [w0, w1, ctx0..ctx9]
//  W_g: [100000, 128] f32
//  W_s: [100000, 8, 128] f32
//  out: [16384, 1] f32
//
// Layout: 8 lanes per row (lane owns 16 dims = 4 float4), 4 rows per warp.
// Each LDG.128 instruction moves 4 x 128B coalesced segments (one per row
// group) -- same byte traffic as the 32-lane layout, but warp reductions are
// 3 shuffle steps instead of 5 and all scalar overhead amortizes 4x.
// W_s streamed evict-first (.cs) to keep the 51MB W_g table hot in L2.

#define CTX 10
#define NUM_SENSES 8

#define F4ADD(a, b) { (a).x += (b).x; (a).y += (b).y; (a).z += (b).z; (a).w += (b).w; }
#define F4DOT(a, b) ((a).x*(b).x + (a).y*(b).y + (a).z*(b).z + (a).w*(b).w)

__global__ void __launch_bounds__(128, 6)
sense_embedding_kernel(const int4* __restrict__ x4,
                       const float4* __restrict__ Wg,
                       const float4* __restrict__ Ws,
                       float* __restrict__ out,
                       int batch)
{
    int warp = (blockIdx.x * blockDim.x + threadIdx.x) >> 5;
    int lane = threadIdx.x & 31;
    int g = lane >> 3;      // row group 0..3 within warp
    int j = lane & 7;       // lane within group; owns float4 slots j, j+8, j+16, j+24
    int row = (warp << 2) + g;
    if (row >= batch) return;

    // x row = 12 ints = 3 x int4 (broadcast within the 8-lane group)
    const int4* xr = x4 + (size_t)row * 3;
    int4 xa = __ldg(&xr[0]);
    int4 xb = __ldg(&xr[1]);
    int4 xc = __ldg(&xr[2]);
    int w0 = xa.x, w1 = xa.y;
    int toks[CTX] = { xa.z, xa.w, xb.x, xb.y, xb.z, xb.w, xc.x, xc.y, xc.z, xc.w };

    // ---- sum_context over this lane's 16 dims ----
    float4 a0 = make_float4(0.f,0.f,0.f,0.f), a1 = a0, a2 = a0, a3 = a0;
#pragma unroll
    for (int i = 0; i < CTX; i++) {
        const float4* r = Wg + (size_t)toks[i] * 32 + j;
        float4 v0 = __ldg(&r[0]);
        float4 v1 = __ldg(&r[8]);
        float4 v2 = __ldg(&r[16]);
        float4 v3 = __ldg(&r[24]);
        F4ADD(a0, v0); F4ADD(a1, v1); F4ADD(a2, v2); F4ADD(a3, v3);
    }

    // ---- stream 8 sense vectors (evict-first), per-lane partial dots ----
    const float4* ws_base = Ws + (size_t)w0 * (NUM_SENSES * 32) + j;
    float partial[NUM_SENSES];
#pragma unroll
    for (int s = 0; s < NUM_SENSES; s++) {
        const float4* r = ws_base + s * 32;
        float4 v0 = __ldcs(&r[0]);
        float4 v1 = __ldcs(&r[8]);
        float4 v2 = __ldcs(&r[16]);
        float4 v3 = __ldcs(&r[24]);
        partial[s] = F4DOT(v0, a0) + F4DOT(v1, a1) + F4DOT(v2, a2) + F4DOT(v3, a3);
    }

    // ---- 3-step butterfly per sense (stays inside 8-lane group);
    //      bitwise-identical in all lanes, so argmax is group-uniform ----
    float best = -INFINITY;
    int bestk = 0;
#pragma unroll
    for (int s = 0; s < NUM_SENSES; s++) {
        float p = partial[s];
        p += __shfl_xor_sync(0xffffffffu, p, 4);
        p += __shfl_xor_sync(0xffffffffu, p, 2);
        p += __shfl_xor_sync(0xffffffffu, p, 1);
        if (p > best) { best = p; bestk = s; }  // first max wins (jnp.argmax)
    }

    // ---- reload chosen sense (L1/L2 hit) + target row; final dot ----
    const float4* rc = ws_base + bestk * 32;
    const float4* rt = Wg + (size_t)w1 * 32 + j;
    float4 c0 = __ldg(&rc[0]),  t0 = __ldg(&rt[0]);
    float4 c1 = __ldg(&rc[8]),  t1 = __ldg(&rt[8]);
    float4 c2 = __ldg(&rc[16]), t2 = __ldg(&rt[16]);
    float4 c3 = __ldg(&rc[24]), t3 = __ldg(&rt[24]);

    float d = F4DOT(c0, t0) + F4DOT(c1, t1) + F4DOT(c2, t2) + F4DOT(c3, t3);
    d += __shfl_xor_sync(0xffffffffu, d, 4);
    d += __shfl_xor_sync(0xffffffffu, d, 2);
    d += __shfl_xor_sync(0xffffffffu, d, 1);

    if (j == 0)
        out[row] = 1.0f / (1.0f + __expf(-d));
}

extern "C" void kernel_launch(void* const* d_in, const int* in_sizes, int n_in,
                              void* d_out, int out_size)
{
    const int4*   x  = (const int4*)d_in[0];
    const float4* Wg = (const float4*)d_in[1];
    const float4* Ws = (const float4*)d_in[2];
    float* out = (float*)d_out;

    int batch = in_sizes[0] / (2 + CTX);           // 16384
    int rows_per_warp = 4;
    int warps = (batch + rows_per_warp - 1) / rows_per_warp;   // 4096
    int threads = 128;                              // 4 warps/block
    int blocks = (warps * 32 + threads - 1) / threads;          // 1024
    sense_embedding_kernel<<<blocks, threads>>>(x, Wg, Ws, out, batch);
}

// round 5
// speedup vs baseline: 1.0017x; 1.0017x over previous
#include <cuda_runtime.h>
#include <math.h>

// SenseEmbedding:
//  x:   [16384, 12] int32   -- [w0, w1, ctx0..ctx9]
//  W_g: [100000, 128] f32
//  W_s: [100000, 8, 128] f32
//  out: [16384, 1] f32
//
// One warp per row (lane = float4 slice; every gather = coalesced 512B).
// Steady state is L2-bandwidth bound. Residency plan: W_g rows are loaded
// with an L2 evict_last policy (pinned hot, ~43MB touched), W_s with default
// policy so its ~61MB touched blocks settle into remaining L2 capacity
// across graph replays. Touched set (~104MB) < L2 (126MB) -> steady-state
// DRAM fills ~0, LTS traffic drops from ~222MB to ~160MB per pass.

#define CTX 10
#define NUM_SENSES 8
#define VEC4 32  // 128 floats = 32 float4

__device__ __forceinline__ float4 ldg_pin(const float4* p, unsigned long long pol)
{
    float4 v;
    asm("ld.global.nc.L2::cache_hint.v4.f32 {%0,%1,%2,%3}, [%4], %5;"
        : "=f"(v.x), "=f"(v.y), "=f"(v.z), "=f"(v.w)
        : "l"(p), "l"(pol));
    return v;
}

__global__ void __launch_bounds__(256, 4)
sense_embedding_kernel(const int4* __restrict__ x4,
                       const float4* __restrict__ Wg,
                       const float4* __restrict__ Ws,
                       float* __restrict__ out,
                       int batch)
{
    int warp = (blockIdx.x * blockDim.x + threadIdx.x) >> 5;
    int lane = threadIdx.x & 31;
    if (warp >= batch) return;

    // L2 evict_last policy for the hot W_g table
    unsigned long long pol;
    asm("createpolicy.fractional.L2::evict_last.b64 %0, 1.0;" : "=l"(pol));

    // x row = 12 ints = 3 x int4
    const int4* xr = x4 + (size_t)warp * 3;
    int4 xa = __ldg(&xr[0]);
    int4 xb = __ldg(&xr[1]);
    int4 xc = __ldg(&xr[2]);
    int w0 = xa.x, w1 = xa.y;
    int toks[CTX] = { xa.z, xa.w, xb.x, xb.y, xb.z, xb.w, xc.x, xc.y, xc.z, xc.w };

    // ---- issue all independent gathers up front (19 x LDG.128) ----
    float4 tv = ldg_pin(&Wg[(size_t)w1 * VEC4 + lane], pol);   // target row

    float4 c[CTX];
#pragma unroll
    for (int i = 0; i < CTX; i++)
        c[i] = ldg_pin(&Wg[(size_t)toks[i] * VEC4 + lane], pol);

    const float4* ws_row = Ws + (size_t)w0 * (NUM_SENSES * VEC4) + lane;
    float4 v[NUM_SENSES];
#pragma unroll
    for (int s = 0; s < NUM_SENSES; s++)
        v[s] = __ldg(&ws_row[s * VEC4]);      // default policy: may stay L2-resident

    // ---- sum_context ----
    float4 acc = c[0];
#pragma unroll
    for (int i = 1; i < CTX; i++) {
        acc.x += c[i].x; acc.y += c[i].y; acc.z += c[i].z; acc.w += c[i].w;
    }

    // ---- per-lane partial dots ----
    float partial[NUM_SENSES];
#pragma unroll
    for (int s = 0; s < NUM_SENSES; s++)
        partial[s] = v[s].x * acc.x + v[s].y * acc.y
                   + v[s].z * acc.z + v[s].w * acc.w;

    // ---- warp-reduce each score; argmax (first max wins, like jnp.argmax) ----
    float best = -INFINITY;
    int bestk = 0;
#pragma unroll
    for (int s = 0; s < NUM_SENSES; s++) {
        float p = partial[s];
        p += __shfl_xor_sync(0xffffffffu, p, 16);
        p += __shfl_xor_sync(0xffffffffu, p, 8);
        p += __shfl_xor_sync(0xffffffffu, p, 4);
        p += __shfl_xor_sync(0xffffffffu, p, 2);
        p += __shfl_xor_sync(0xffffffffu, p, 1);
        if (p > best) { best = p; bestk = s; }  // warp-uniform
    }

    // ---- chosen sense already in registers; select + final dot ----
    float4 ch = v[0];
#pragma unroll
    for (int s = 1; s < NUM_SENSES; s++)
        if (s == bestk) ch = v[s];

    float d = ch.x * tv.x + ch.y * tv.y + ch.z * tv.z + ch.w * tv.w;
    d += __shfl_xor_sync(0xffffffffu, d, 16);
    d += __shfl_xor_sync(0xffffffffu, d, 8);
    d += __shfl_xor_sync(0xffffffffu, d, 4);
    d += __shfl_xor_sync(0xffffffffu, d, 2);
    d += __shfl_xor_sync(0xffffffffu, d, 1);

    if (lane == 0)
        out[warp] = 1.0f / (1.0f + __expf(-d));
}

extern "C" void kernel_launch(void* const* d_in, const int* in_sizes, int n_in,
                              void* d_out, int out_size)
{
    const int4*   x  = (const int4*)d_in[0];
    const float4* Wg = (const float4*)d_in[1];
    const float4* Ws = (const float4*)d_in[2];
    float* out = (float*)d_out;

    int batch = in_sizes[0] / (2 + CTX);   // 16384
    int threads = 256;                      // 8 warps/block
    int blocks = (batch * 32 + threads - 1) / threads;
    sense_embedding_kernel<<<blocks, threads>>>(x, Wg, Ws, out, batch);
}

// round 6
// speedup vs baseline: 1.0169x; 1.0152x over previous
#include <cuda_runtime.h>
#include <math.h>

// SenseEmbedding:
//  x:   [16384, 12] int32   -- [w0, w1, ctx0..ctx9]
//  W_g: [100000, 128] f32
//  W_s: [100000, 8, 128] f32
//  out: [16384, 1] f32
//
// One warp per row (lane = float4 slice; every gather = coalesced 512B).
// Steady state is LTS-bound at ~221MB/pass when W_s (61MB cyclic sweep)
// misses L2 every replay. Fix: pin W_s lines with an L2 evict_last policy so
// the sweep becomes L2-resident across graph replays; W_g's random gathers
// (43MB touched) live in the remaining ~65MB with default policy, where
// random access (unlike a cyclic sweep) retains fine under pseudo-LRU.

#define CTX 10
#define NUM_SENSES 8
#define VEC4 32  // 128 floats = 32 float4

__device__ __forceinline__ float4 ldg_pin(const float4* p, unsigned long long pol)
{
    float4 v;
    asm("ld.global.nc.L2::cache_hint.v4.f32 {%0,%1,%2,%3}, [%4], %5;"
        : "=f"(v.x), "=f"(v.y), "=f"(v.z), "=f"(v.w)
        : "l"(p), "l"(pol));
    return v;
}

__global__ void __launch_bounds__(256, 4)
sense_embedding_kernel(const int4* __restrict__ x4,
                       const float4* __restrict__ Wg,
                       const float4* __restrict__ Ws,
                       float* __restrict__ out,
                       int batch)
{
    int warp = (blockIdx.x * blockDim.x + threadIdx.x) >> 5;
    int lane = threadIdx.x & 31;
    if (warp >= batch) return;

    // L2 evict_last policy for the W_s sweep (cyclic pattern: must be pinned
    // to survive across replays; default LRU would retain none of it).
    unsigned long long pol;
    asm("createpolicy.fractional.L2::evict_last.b64 %0, 1.0;" : "=l"(pol));

    // x row = 12 ints = 3 x int4
    const int4* xr = x4 + (size_t)warp * 3;
    int4 xa = __ldg(&xr[0]);
    int4 xb = __ldg(&xr[1]);
    int4 xc = __ldg(&xr[2]);
    int w0 = xa.x, w1 = xa.y;
    int toks[CTX] = { xa.z, xa.w, xb.x, xb.y, xb.z, xb.w, xc.x, xc.y, xc.z, xc.w };

    // ---- issue all independent gathers up front (19 x LDG.128) ----
    float4 tv = __ldg(&Wg[(size_t)w1 * VEC4 + lane]);   // target row

    float4 c[CTX];
#pragma unroll
    for (int i = 0; i < CTX; i++)
        c[i] = __ldg(&Wg[(size_t)toks[i] * VEC4 + lane]);

    const float4* ws_row = Ws + (size_t)w0 * (NUM_SENSES * VEC4) + lane;
    float4 v[NUM_SENSES];
#pragma unroll
    for (int s = 0; s < NUM_SENSES; s++)
        v[s] = ldg_pin(&ws_row[s * VEC4], pol);   // pinned L2-resident

    // ---- sum_context ----
    float4 acc = c[0];
#pragma unroll
    for (int i = 1; i < CTX; i++) {
        acc.x += c[i].x; acc.y += c[i].y; acc.z += c[i].z; acc.w += c[i].w;
    }

    // ---- per-lane partial dots ----
    float partial[NUM_SENSES];
#pragma unroll
    for (int s = 0; s < NUM_SENSES; s++)
        partial[s] = v[s].x * acc.x + v[s].y * acc.y
                   + v[s].z * acc.z + v[s].w * acc.w;

    // ---- warp-reduce each score; argmax (first max wins, like jnp.argmax) ----
    float best = -INFINITY;
    int bestk = 0;
#pragma unroll
    for (int s = 0; s < NUM_SENSES; s++) {
        float p = partial[s];
        p += __shfl_xor_sync(0xffffffffu, p, 16);
        p += __shfl_xor_sync(0xffffffffu, p, 8);
        p += __shfl_xor_sync(0xffffffffu, p, 4);
        p += __shfl_xor_sync(0xffffffffu, p, 2);
        p += __shfl_xor_sync(0xffffffffu, p, 1);
        if (p > best) { best = p; bestk = s; }  // warp-uniform
    }

    // ---- chosen sense already in registers; select + final dot ----
    float4 ch = v[0];
#pragma unroll
    for (int s = 1; s < NUM_SENSES; s++)
        if (s == bestk) ch = v[s];

    float d = ch.x * tv.x + ch.y * tv.y + ch.z * tv.z + ch.w * tv.w;
    d += __shfl_xor_sync(0xffffffffu, d, 16);
    d += __shfl_xor_sync(0xffffffffu, d, 8);
    d += __shfl_xor_sync(0xffffffffu, d, 4);
    d += __shfl_xor_sync(0xffffffffu, d, 2);
    d += __shfl_xor_sync(0xffffffffu, d, 1);

    if (lane == 0)
        out[warp] = 1.0f / (1.0f + __expf(-d));
}

extern "C" void kernel_launch(void* const* d_in, const int* in_sizes, int n_in,
                              void* d_out, int out_size)
{
    const int4*   x  = (const int4*)d_in[0];
    const float4* Wg = (const float4*)d_in[1];
    const float4* Ws = (const float4*)d_in[2];
    float* out = (float*)d_out;

    int batch = in_sizes[0] / (2 + CTX);   // 16384
    int threads = 256;                      // 8 warps/block
    int blocks = (batch * 32 + threads - 1) / threads;
    sense_embedding_kernel<<<blocks, threads>>>(x, Wg, Ws, out, batch);
}

// round 7
// speedup vs baseline: 1.1404x; 1.1214x over previous
#include <cuda_runtime.h>
#include <math.h>

// SenseEmbedding:
//  x:   [16384, 12] int32   -- [w0, w1, ctx0..ctx9]
//  W_g: [100000, 128] f32
//  W_s: [100000, 8, 128] f32
//  out: [16384, 1] f32
//
// One warp per row (lane = float4 slice -> every gather is a coalesced 512B
// access). W_s streamed with evict-first (.cs): protects the hot W_g table in
// L2 (L2 pin policies measured as useless without a persisting carveout).
// Persistent grid: exactly one wave (148 SMs x 4 blocks), each warp
// grid-strides over ~3.5 rows -- removes wave transitions, tail raggedness,
// and late-CTA L1tex queue pileup. Steady state is LTS-bound (~159MB/pass).

#define CTX 10
#define NUM_SENSES 8
#define VEC4 32  // 128 floats = 32 float4

#define NBLOCKS 592   // 148 SMs * 4 resident blocks
#define NTHREADS 256  // 8 warps/block

__global__ void __launch_bounds__(NTHREADS, 4)
sense_embedding_kernel(const int4* __restrict__ x4,
                       const float4* __restrict__ Wg,
                       const float4* __restrict__ Ws,
                       float* __restrict__ out,
                       int batch)
{
    int warp0 = (blockIdx.x * NTHREADS + threadIdx.x) >> 5;
    int lane = threadIdx.x & 31;
    const int warp_stride = (NBLOCKS * NTHREADS) >> 5;   // 4736 warps total

    for (int row = warp0; row < batch; row += warp_stride) {
        // x row = 12 ints = 3 x int4
        const int4* xr = x4 + (size_t)row * 3;
        int4 xa = __ldg(&xr[0]);
        int4 xb = __ldg(&xr[1]);
        int4 xc = __ldg(&xr[2]);
        int w0 = xa.x, w1 = xa.y;
        int toks[CTX] = { xa.z, xa.w, xb.x, xb.y, xb.z,
                          xb.w, xc.x, xc.y, xc.z, xc.w };

        // ---- independent gathers; sense vectors + target issued alongside ----
        float4 tv = __ldg(&Wg[(size_t)w1 * VEC4 + lane]);   // target row

        const float4* ws_row = Ws + (size_t)w0 * (NUM_SENSES * VEC4) + lane;
        float4 v[NUM_SENSES];
#pragma unroll
        for (int s = 0; s < NUM_SENSES; s++)
            v[s] = __ldcs(&ws_row[s * VEC4]);               // evict-first stream

        float4 acc = make_float4(0.f, 0.f, 0.f, 0.f);
#pragma unroll
        for (int i = 0; i < CTX; i++) {
            float4 cv = __ldg(&Wg[(size_t)toks[i] * VEC4 + lane]);
            acc.x += cv.x; acc.y += cv.y; acc.z += cv.z; acc.w += cv.w;
        }

        // ---- per-lane partial dots ----
        float partial[NUM_SENSES];
#pragma unroll
        for (int s = 0; s < NUM_SENSES; s++)
            partial[s] = v[s].x * acc.x + v[s].y * acc.y
                       + v[s].z * acc.z + v[s].w * acc.w;

        // ---- warp-reduce each score; argmax (first max wins) ----
        float best = -INFINITY;
        int bestk = 0;
#pragma unroll
        for (int s = 0; s < NUM_SENSES; s++) {
            float p = partial[s];
            p += __shfl_xor_sync(0xffffffffu, p, 16);
            p += __shfl_xor_sync(0xffffffffu, p, 8);
            p += __shfl_xor_sync(0xffffffffu, p, 4);
            p += __shfl_xor_sync(0xffffffffu, p, 2);
            p += __shfl_xor_sync(0xffffffffu, p, 1);
            if (p > best) { best = p; bestk = s; }  // warp-uniform
        }

        // ---- chosen sense already in registers; select + final dot ----
        float4 ch = v[0];
#pragma unroll
        for (int s = 1; s < NUM_SENSES; s++)
            if (s == bestk) ch = v[s];

        float d = ch.x * tv.x + ch.y * tv.y + ch.z * tv.z + ch.w * tv.w;
        d += __shfl_xor_sync(0xffffffffu, d, 16);
        d += __shfl_xor_sync(0xffffffffu, d, 8);
        d += __shfl_xor_sync(0xffffffffu, d, 4);
        d += __shfl_xor_sync(0xffffffffu, d, 2);
        d += __shfl_xor_sync(0xffffffffu, d, 1);

        if (lane == 0)
            out[row] = 1.0f / (1.0f + __expf(-d));
    }
}

extern "C" void kernel_launch(void* const* d_in, const int* in_sizes, int n_in,
                              void* d_out, int out_size)
{
    const int4*   x  = (const int4*)d_in[0];
    const float4* Wg = (const float4*)d_in[1];
    const float4* Ws = (const float4*)d_in[2];
    float* out = (float*)d_out;

    int batch = in_sizes[0] / (2 + CTX);   // 16384
    sense_embedding_kernel<<<NBLOCKS, NTHREADS>>>(x, Wg, Ws, out, batch);
}